// round 1
// baseline (speedup 1.0000x reference)
#include <cuda_runtime.h>
#include <cuda_bf16.h>

// ---------------- problem constants ----------------
#define BB   2
#define SS   1024
#define BS   2048          // B*S
#define DIM  4096
#define HH   32
#define QL   1536
#define KVL  512
#define NOPE 128
#define ROPE 64
#define VD   128
#define QKH  192           // NOPE+ROPE
#define CAT  576           // KVL+ROPE
#define QD   6144          // H*QKH

#define NEGV   (-1e9f)
#define SCALEV 0.07216878364870322f   // 192^-0.5
#define EPSV   1e-6f

// ---------------- scratch (device globals; no allocation allowed) ----------
__device__ float g_qlora[(long long)BS * QL];
__device__ float g_kv   [(long long)BS * CAT];
__device__ float g_kvcat[(long long)BS * CAT];          // [norm(c_kv) | rope(k_pe)]
__device__ float g_q    [(long long)BS * QD];
__device__ float g_qcat [(long long)BS * HH * CAT];     // [q_abs | rope(q_pe)] per head
__device__ float g_scores[64LL * 1024 * 1024];          // (b,h,s,t)
__device__ float g_attn [(long long)BS * HH * KVL];     // (bs,h,c)
__device__ float g_proj [(long long)BS * DIM];          // (bs, h*VD+d)

// ---------------- generic tiled GEMM ----------------
// C[m,n] (+epilogue) = sum_k A[m,k] * B(k,n)
// TB: B stored [N,K] row-major (i.e. compute A @ B^T)
// EPI==1: scores epilogue (v*SCALE + causal NEG), with fully-masked tile skip
// CK: causal K-bound (k loop limited to m0+BM) for P@V
static const int BM = 128, BN = 128, BK = 16;

template<bool TB, int EPI, bool CK>
__global__ __launch_bounds__(256, 2)
void gemm_k(const float* __restrict__ A, const float* __restrict__ Bp,
            float* __restrict__ C,
            int M, int N, int K,
            int lda, int ldb, int ldc,
            long long bA1, long long bA2,
            long long bB1, long long bB2,
            long long bC1, long long bC2, int nz2)
{
    const int z  = blockIdx.z;
    const int z1 = z / nz2;
    const int z2 = z - z1 * nz2;
    A  += z1 * bA1 + z2 * bA2;
    Bp += z1 * bB1 + z2 * bB2;
    C  += z1 * bC1 + z2 * bC2;

    const int m0  = blockIdx.y * BM;
    const int n0  = blockIdx.x * BN;
    const int tid = threadIdx.x;

    if (EPI == 1 && n0 >= m0 + BM) {
        // tile entirely above the diagonal: all masked
        for (int e = tid; e < BM * BN; e += 256) {
            int r = e >> 7, c = e & 127;
            if (n0 + c < N) C[(long long)(m0 + r) * ldc + n0 + c] = NEGV;
        }
        return;
    }

    __shared__ float As[BK][BM + 4];
    __shared__ float Bs[BK][BN + 4];

    float acc[8][8];
#pragma unroll
    for (int i = 0; i < 8; i++)
#pragma unroll
        for (int j = 0; j < 8; j++) acc[i][j] = 0.f;

    int Keff = K;
    if (CK) { int km = m0 + BM; Keff = (km < K) ? km : K; }

    const int ty = tid >> 4;          // 0..15
    const int tx = tid & 15;          // 0..15
    const int am = tid >> 2;          // 0..63 (rows for A / B-transposed loads)
    const int ak = (tid & 3) << 2;    // 0,4,8,12
    const int bk = tid >> 5;          // 0..7  (rows for B non-transposed loads)
    const int bn = (tid & 31) << 2;   // 0..124

    for (int k0 = 0; k0 < Keff; k0 += BK) {
        // ---- load A tile (M,K assumed multiples of 128/16 — true for all calls)
#pragma unroll
        for (int p = 0; p < 2; p++) {
            int m = am + p * 64;
            float4 v = *reinterpret_cast<const float4*>(
                A + (long long)(m0 + m) * lda + k0 + ak);
            As[ak + 0][m] = v.x; As[ak + 1][m] = v.y;
            As[ak + 2][m] = v.z; As[ak + 3][m] = v.w;
        }
        // ---- load B tile
        if (!TB) {
#pragma unroll
            for (int p = 0; p < 2; p++) {
                int k = bk + p * 8;
                float4 v;
                if (n0 + bn + 3 < N) {
                    v = *reinterpret_cast<const float4*>(
                        Bp + (long long)(k0 + k) * ldb + n0 + bn);
                } else {
                    v.x = (n0 + bn + 0 < N) ? Bp[(long long)(k0 + k) * ldb + n0 + bn + 0] : 0.f;
                    v.y = (n0 + bn + 1 < N) ? Bp[(long long)(k0 + k) * ldb + n0 + bn + 1] : 0.f;
                    v.z = (n0 + bn + 2 < N) ? Bp[(long long)(k0 + k) * ldb + n0 + bn + 2] : 0.f;
                    v.w = (n0 + bn + 3 < N) ? Bp[(long long)(k0 + k) * ldb + n0 + bn + 3] : 0.f;
                }
                Bs[k][bn + 0] = v.x; Bs[k][bn + 1] = v.y;
                Bs[k][bn + 2] = v.z; Bs[k][bn + 3] = v.w;
            }
        } else {
#pragma unroll
            for (int p = 0; p < 2; p++) {
                int n = am + p * 64;
                float4 v = make_float4(0.f, 0.f, 0.f, 0.f);
                if (n0 + n < N)
                    v = *reinterpret_cast<const float4*>(
                        Bp + (long long)(n0 + n) * ldb + k0 + ak);
                Bs[ak + 0][n] = v.x; Bs[ak + 1][n] = v.y;
                Bs[ak + 2][n] = v.z; Bs[ak + 3][n] = v.w;
            }
        }
        __syncthreads();

#pragma unroll
        for (int k = 0; k < BK; k++) {
            float af[8], bf[8];
            *reinterpret_cast<float4*>(&af[0]) = *reinterpret_cast<const float4*>(&As[k][ty * 8]);
            *reinterpret_cast<float4*>(&af[4]) = *reinterpret_cast<const float4*>(&As[k][ty * 8 + 4]);
            *reinterpret_cast<float4*>(&bf[0]) = *reinterpret_cast<const float4*>(&Bs[k][tx * 8]);
            *reinterpret_cast<float4*>(&bf[4]) = *reinterpret_cast<const float4*>(&Bs[k][tx * 8 + 4]);
#pragma unroll
            for (int i = 0; i < 8; i++)
#pragma unroll
                for (int j = 0; j < 8; j++)
                    acc[i][j] += af[i] * bf[j];
        }
        __syncthreads();
    }

    // ---- store
#pragma unroll
    for (int i = 0; i < 8; i++) {
        int m = m0 + ty * 8 + i;
        long long ro = (long long)m * ldc;
#pragma unroll
        for (int jj = 0; jj < 2; jj++) {
            int n = n0 + tx * 8 + jj * 4;
            float4 v = make_float4(acc[i][jj * 4 + 0], acc[i][jj * 4 + 1],
                                   acc[i][jj * 4 + 2], acc[i][jj * 4 + 3]);
            if (EPI == 1) {
                v.x = v.x * SCALEV + ((n + 0 > m) ? NEGV : 0.f);
                v.y = v.y * SCALEV + ((n + 1 > m) ? NEGV : 0.f);
                v.z = v.z * SCALEV + ((n + 2 > m) ? NEGV : 0.f);
                v.w = v.w * SCALEV + ((n + 3 > m) ? NEGV : 0.f);
            }
            if (n + 3 < N) {
                *reinterpret_cast<float4*>(C + ro + n) = v;
            } else {
                if (n + 0 < N) C[ro + n + 0] = v.x;
                if (n + 1 < N) C[ro + n + 1] = v.y;
                if (n + 2 < N) C[ro + n + 2] = v.z;
                if (n + 3 < N) C[ro + n + 3] = v.w;
            }
        }
    }
}

// ---------------- rmsnorm (in place), one block per row ----------------
__global__ void rmsnorm_k(float* __restrict__ x, const float* __restrict__ w, int len)
{
    float* row = x + (long long)blockIdx.x * len;
    const int tid = threadIdx.x;
    float ss = 0.f;
    for (int i = tid; i < len; i += 256) { float v = row[i]; ss += v * v; }
    __shared__ float red[8];
    __shared__ float sc_s;
#pragma unroll
    for (int o = 16; o; o >>= 1) ss += __shfl_xor_sync(0xffffffffu, ss, o);
    if ((tid & 31) == 0) red[tid >> 5] = ss;
    __syncthreads();
    if (tid == 0) {
        float t = 0.f;
#pragma unroll
        for (int i = 0; i < 8; i++) t += red[i];
        sc_s = rsqrtf(t / (float)len + EPSV);
    }
    __syncthreads();
    float sc = sc_s;
    for (int i = tid; i < len; i += 256) row[i] = row[i] * sc * w[i];
}

// ---- kv post: rmsnorm(c_kv)*w -> kvcat[0:512]; rope(k_pe) -> kvcat[512:576]
__global__ void kvpost_k(const float* __restrict__ kv, const float* __restrict__ w,
                         const float* __restrict__ fc, float* __restrict__ out)
{
    const int bs = blockIdx.x;
    const float* row = kv + (long long)bs * CAT;
    float* o = out + (long long)bs * CAT;
    const int tid = threadIdx.x;
    float ss = 0.f;
    for (int i = tid; i < KVL; i += 256) { float v = row[i]; ss += v * v; }
    __shared__ float red[8];
    __shared__ float sc_s;
#pragma unroll
    for (int oo = 16; oo; oo >>= 1) ss += __shfl_xor_sync(0xffffffffu, ss, oo);
    if ((tid & 31) == 0) red[tid >> 5] = ss;
    __syncthreads();
    if (tid == 0) {
        float t = 0.f;
#pragma unroll
        for (int i = 0; i < 8; i++) t += red[i];
        sc_s = rsqrtf(t / (float)KVL + EPSV);
    }
    __syncthreads();
    float sc = sc_s;
    for (int i = tid; i < KVL; i += 256) o[i] = row[i] * sc * w[i];
    if (tid < 32) {
        int s = bs & (SS - 1);
        float e  = row[KVL + 2 * tid];
        float od = row[KVL + 2 * tid + 1];
        float c  = fc[s * ROPE + 2 * tid];
        float sn = fc[s * ROPE + 2 * tid + 1];
        o[KVL + 2 * tid]     = e * c - od * sn;
        o[KVL + 2 * tid + 1] = e * sn + od * c;
    }
}

// ---- rope on q_pe, written into qcat[...,512:576] ----
__global__ void ropeq_k(const float* __restrict__ q, const float* __restrict__ fc,
                        float* __restrict__ qcat)
{
    const int bs = blockIdx.x;
    const int s = bs & (SS - 1);
    for (int t = threadIdx.x; t < HH * (ROPE / 2); t += 256) {
        int h = t >> 5, i = t & 31;
        const float* src = q + (long long)bs * QD + h * QKH + NOPE + 2 * i;
        float e = src[0], o = src[1];
        float c  = fc[s * ROPE + 2 * i];
        float sn = fc[s * ROPE + 2 * i + 1];
        float* dst = qcat + (long long)bs * (HH * CAT) + h * CAT + KVL + 2 * i;
        dst[0] = e * c - o * sn;
        dst[1] = e * sn + o * c;
    }
}

// ---- softmax over rows of 1024 ----
__global__ void softmax_k(float* __restrict__ S)
{
    float* row = S + (long long)blockIdx.x * 1024;
    const int tid = threadIdx.x;
    float v[4];
    float mx = -3.4e38f;
#pragma unroll
    for (int j = 0; j < 4; j++) { v[j] = row[tid + 256 * j]; mx = fmaxf(mx, v[j]); }
    __shared__ float red[8];
    __shared__ float bval;
#pragma unroll
    for (int o = 16; o; o >>= 1) mx = fmaxf(mx, __shfl_xor_sync(0xffffffffu, mx, o));
    if ((tid & 31) == 0) red[tid >> 5] = mx;
    __syncthreads();
    if (tid == 0) {
        float t = red[0];
#pragma unroll
        for (int i = 1; i < 8; i++) t = fmaxf(t, red[i]);
        bval = t;
    }
    __syncthreads();
    mx = bval;
    float sum = 0.f;
#pragma unroll
    for (int j = 0; j < 4; j++) { v[j] = __expf(v[j] - mx); sum += v[j]; }
    __syncthreads();
#pragma unroll
    for (int o = 16; o; o >>= 1) sum += __shfl_xor_sync(0xffffffffu, sum, o);
    if ((tid & 31) == 0) red[tid >> 5] = sum;
    __syncthreads();
    if (tid == 0) {
        float t = 0.f;
#pragma unroll
        for (int i = 0; i < 8; i++) t += red[i];
        bval = 1.f / t;
    }
    __syncthreads();
    float inv = bval;
#pragma unroll
    for (int j = 0; j < 4; j++) row[tid + 256 * j] = v[j] * inv;
}

// ---------------- host ----------------
extern "C" void kernel_launch(void* const* d_in, const int* in_sizes, int n_in,
                              void* d_out, int out_size)
{
    (void)in_sizes; (void)n_in; (void)out_size;
    const float* x      = (const float*)d_in[0];
    const float* fc     = (const float*)d_in[1];
    /* mask d_in[2] handled analytically (start_pos == 0, causal) */
    const float* wq_a   = (const float*)d_in[3];
    const float* qnw    = (const float*)d_in[4];
    const float* wq_b   = (const float*)d_in[5];
    const float* wkv_a  = (const float*)d_in[6];
    const float* kvnw   = (const float*)d_in[7];
    const float* wkv_b  = (const float*)d_in[8];
    const float* wo     = (const float*)d_in[9];
    float* out = (float*)d_out;

    float *qlora, *kv, *kvcat, *q, *qcat, *scores, *attn, *proj;
    cudaGetSymbolAddress((void**)&qlora,  g_qlora);
    cudaGetSymbolAddress((void**)&kv,     g_kv);
    cudaGetSymbolAddress((void**)&kvcat,  g_kvcat);
    cudaGetSymbolAddress((void**)&q,      g_q);
    cudaGetSymbolAddress((void**)&qcat,   g_qcat);
    cudaGetSymbolAddress((void**)&scores, g_scores);
    cudaGetSymbolAddress((void**)&attn,   g_attn);
    cudaGetSymbolAddress((void**)&proj,   g_proj);

    // 1. q_lora = x @ wq_a            [2048,1536] = [2048,4096]@[4096,1536]
    gemm_k<false, 0, false><<<dim3(12, 16, 1), 256>>>(
        x, wq_a, qlora, BS, QL, DIM, DIM, QL, QL, 0, 0, 0, 0, 0, 0, 1);
    // 2. kv = x @ wkv_a               [2048,576]
    gemm_k<false, 0, false><<<dim3(5, 16, 1), 256>>>(
        x, wkv_a, kv, BS, CAT, DIM, DIM, CAT, CAT, 0, 0, 0, 0, 0, 0, 1);
    // 3. rmsnorm(q_lora) in place
    rmsnorm_k<<<BS, 256>>>(qlora, qnw, QL);
    // 4. kv_norm + rope(k_pe) -> kvcat
    kvpost_k<<<BS, 256>>>(kv, kvnw, fc, kvcat);
    // 5. q = qlora_n @ wq_b           [2048,6144]
    gemm_k<false, 0, false><<<dim3(48, 16, 1), 256>>>(
        qlora, wq_b, q, BS, QD, QL, QL, QD, QD, 0, 0, 0, 0, 0, 0, 1);
    // 6. rope(q_pe) -> qcat[...,512:576]
    ropeq_k<<<BS, 256>>>(q, fc, qcat);
    // 7. q_abs (per head): qcat[...,0:512] = q_nope @ wkv_b[h,:128,:]
    gemm_k<false, 0, false><<<dim3(4, 16, HH), 256>>>(
        q, wkv_b, qcat, BS, KVL, NOPE,
        QD, KVL, HH * CAT,
        0, QKH, 0, (long long)(NOPE + VD) * KVL, 0, CAT, HH);
    // 8. scores (per b,h) = qcat @ kvcat^T, *SCALE + causal NEG
    gemm_k<true, 1, false><<<dim3(8, 8, BB * HH), 256>>>(
        qcat, kvcat, scores, SS, SS, CAT,
        HH * CAT, CAT, SS,
        (long long)SS * HH * CAT, CAT,
        (long long)SS * CAT, 0,
        (long long)HH * SS * SS, (long long)SS * SS, HH);
    // 9. softmax
    softmax_k<<<BB * HH * SS, 256>>>(scores);
    // 10. attn = P @ kv_norm (causal K-bound)
    gemm_k<false, 0, true><<<dim3(4, 8, BB * HH), 256>>>(
        scores, kvcat, attn, SS, KVL, SS,
        SS, CAT, HH * KVL,
        (long long)HH * SS * SS, (long long)SS * SS,
        (long long)SS * CAT, 0,
        (long long)SS * HH * KVL, KVL, HH);
    // 11. per-head V up-proj: proj[:, h*128+d] = attn_h @ wkv_b[h,128:,:]^T
    gemm_k<true, 0, false><<<dim3(1, 16, HH), 256>>>(
        attn, wkv_b + (long long)NOPE * KVL, proj, BS, VD, KVL,
        HH * KVL, KVL, DIM,
        0, KVL, 0, (long long)(NOPE + VD) * KVL, 0, VD, HH);
    // 12. out = proj @ wo             [2048,4096]
    gemm_k<false, 0, false><<<dim3(32, 16, 1), 256>>>(
        proj, wo, out, BS, DIM, DIM, DIM, DIM, DIM, 0, 0, 0, 0, 0, 0, 1);
}

// round 3
// speedup vs baseline: 2.0339x; 2.0339x over previous
#include <cuda_runtime.h>
#include <cuda_bf16.h>
#include <cstdint>

// ---------------- problem constants ----------------
#define BB   2
#define SS   1024
#define BS   2048          // B*S
#define DIM  4096
#define HH   32
#define QL   1536
#define KVL  512
#define NOPE 128
#define ROPE 64
#define VD   128
#define QKH  192           // NOPE+ROPE
#define CAT  576           // KVL+ROPE
#define QD   6144          // H*QKH

#define NEGV   (-1e9f)
#define SCALEV 0.07216878364870322f   // 192^-0.5
#define EPSV   1e-6f

// ---------------- scratch (device globals; no allocation allowed) ----------
__device__ float g_qlora[(long long)BS * QL];
__device__ float g_kv   [(long long)BS * CAT];
__device__ float g_kvcat[(long long)BS * CAT];          // [norm(c_kv) | rope(k_pe)]
__device__ float g_q    [(long long)BS * QD];
__device__ float g_qcat [(long long)BS * HH * CAT];     // [q_abs | rope(q_pe)] per head
__device__ float g_scores[64LL * 1024 * 1024];          // (b,h,s,t)
__device__ float g_attn [(long long)BS * HH * KVL];     // (bs,h,c)
__device__ float g_proj [(long long)BS * DIM];          // (bs, h*VD+d)

// ---------------- helpers ----------------
__device__ __forceinline__ float tf32r(float x) {
    uint32_t u;
    asm("cvt.rna.tf32.f32 %0, %1;" : "=r"(u) : "f"(x));
    return __uint_as_float(u);
}

__device__ __forceinline__ void mma8(float c[4], const uint32_t a[4], const uint32_t b[2]) {
    asm volatile(
        "mma.sync.aligned.m16n8k8.row.col.f32.tf32.tf32.f32 "
        "{%0,%1,%2,%3},{%4,%5,%6,%7},{%8,%9},{%0,%1,%2,%3};\n"
        : "+f"(c[0]), "+f"(c[1]), "+f"(c[2]), "+f"(c[3])
        : "r"(a[0]), "r"(a[1]), "r"(a[2]), "r"(a[3]), "r"(b[0]), "r"(b[1]));
}

// ---------------- 3xTF32 tensor-core tiled GEMM ----------------
// C[m,n] = sum_k A[m,k] * B(k,n) ; TB: B stored [N,K] row-major (A @ B^T)
// EPI==1: scores epilogue (v*SCALE + causal NEG) with fully-masked tile skip
// CK: causal K-bound (k limited to m0+128) for P@V
// CTA tile 128x128, BK=16, 8 warps (2m x 4n), warp tile 64x32.
// Precision: x = hi + lo (tf32 RNA split); D += ah*bh + ah*bl + al*bh -> ~fp32.
static const int BM = 128, BN = 128, BK = 16;
#define PA 20      // pitch for [row][k] tiles (A, transposed-B): conflict-free
#define PB 136     // pitch for [k][n] tiles (k-major B): conflict-free

template<bool TB, int EPI, bool CK>
__global__ __launch_bounds__(256, 2)
void gemm_k(const float* __restrict__ A, const float* __restrict__ Bp,
            float* __restrict__ C,
            int M, int N, int K,
            int lda, int ldb, int ldc,
            long long bA1, long long bA2,
            long long bB1, long long bB2,
            long long bC1, long long bC2, int nz2)
{
    const int z  = blockIdx.z;
    const int z1 = z / nz2;
    const int z2 = z - z1 * nz2;
    A  += z1 * bA1 + z2 * bA2;
    Bp += z1 * bB1 + z2 * bB2;
    C  += z1 * bC1 + z2 * bC2;

    const int m0  = blockIdx.y * BM;
    const int n0  = blockIdx.x * BN;
    const int tid = threadIdx.x;

    if (EPI == 1 && n0 >= m0 + BM) {
        for (int e = tid; e < BM * BN; e += 256) {
            int r = e >> 7, c = e & 127;
            if (n0 + c < N) C[(long long)(m0 + r) * ldc + n0 + c] = NEGV;
        }
        return;
    }

    __shared__ float Ah[BM * PA], Al[BM * PA];
    __shared__ float Bh[2560],    Bl[2560];     // max(128*PA, 16*PB)

    const int lane = tid & 31, warp = tid >> 5;
    const int wm = warp >> 2, wn = warp & 3;     // 2 x 4 warp grid
    const int gp = lane >> 2, tg = lane & 3;

    float acc[4][4][4];
#pragma unroll
    for (int i = 0; i < 4; i++)
#pragma unroll
        for (int j = 0; j < 4; j++)
#pragma unroll
            for (int r = 0; r < 4; r++) acc[i][j][r] = 0.f;

    int Keff = K;
    if (CK) { int km = m0 + BM; Keff = (km < K) ? km : K; }

    const int am = tid >> 2;          // 0..63 rows (A / B-transposed loads)
    const int ak = (tid & 3) << 2;    // 0,4,8,12
    const int bk = tid >> 5;          // 0..7  (k-major B loads)
    const int bn = (tid & 31) << 2;   // 0..124

    for (int k0 = 0; k0 < Keff; k0 += BK) {
        // ---- A tile -> [m][k] pitch PA (hi/lo)
#pragma unroll
        for (int p = 0; p < 2; p++) {
            int m = am + (p << 6);
            float4 v = *reinterpret_cast<const float4*>(
                A + (long long)(m0 + m) * lda + k0 + ak);
            float4 h, l;
            h.x = tf32r(v.x); l.x = tf32r(v.x - h.x);
            h.y = tf32r(v.y); l.y = tf32r(v.y - h.y);
            h.z = tf32r(v.z); l.z = tf32r(v.z - h.z);
            h.w = tf32r(v.w); l.w = tf32r(v.w - h.w);
            *reinterpret_cast<float4*>(&Ah[m * PA + ak]) = h;
            *reinterpret_cast<float4*>(&Al[m * PA + ak]) = l;
        }
        // ---- B tile
        if (!TB) {   // gmem [k][n] -> smem [k][n] pitch PB
#pragma unroll
            for (int p = 0; p < 2; p++) {
                int k = bk + (p << 3);
                float4 v;
                if (n0 + bn + 3 < N) {
                    v = *reinterpret_cast<const float4*>(
                        Bp + (long long)(k0 + k) * ldb + n0 + bn);
                } else {
                    v.x = (n0 + bn + 0 < N) ? Bp[(long long)(k0 + k) * ldb + n0 + bn + 0] : 0.f;
                    v.y = (n0 + bn + 1 < N) ? Bp[(long long)(k0 + k) * ldb + n0 + bn + 1] : 0.f;
                    v.z = (n0 + bn + 2 < N) ? Bp[(long long)(k0 + k) * ldb + n0 + bn + 2] : 0.f;
                    v.w = (n0 + bn + 3 < N) ? Bp[(long long)(k0 + k) * ldb + n0 + bn + 3] : 0.f;
                }
                float4 h, l;
                h.x = tf32r(v.x); l.x = tf32r(v.x - h.x);
                h.y = tf32r(v.y); l.y = tf32r(v.y - h.y);
                h.z = tf32r(v.z); l.z = tf32r(v.z - h.z);
                h.w = tf32r(v.w); l.w = tf32r(v.w - h.w);
                *reinterpret_cast<float4*>(&Bh[k * PB + bn]) = h;
                *reinterpret_cast<float4*>(&Bl[k * PB + bn]) = l;
            }
        } else {     // gmem [n][k] -> smem [n][k] pitch PA
#pragma unroll
            for (int p = 0; p < 2; p++) {
                int n = am + (p << 6);
                float4 v = make_float4(0.f, 0.f, 0.f, 0.f);
                if (n0 + n < N)
                    v = *reinterpret_cast<const float4*>(
                        Bp + (long long)(n0 + n) * ldb + k0 + ak);
                float4 h, l;
                h.x = tf32r(v.x); l.x = tf32r(v.x - h.x);
                h.y = tf32r(v.y); l.y = tf32r(v.y - h.y);
                h.z = tf32r(v.z); l.z = tf32r(v.z - h.z);
                h.w = tf32r(v.w); l.w = tf32r(v.w - h.w);
                *reinterpret_cast<float4*>(&Bh[n * PA + ak]) = h;
                *reinterpret_cast<float4*>(&Bl[n * PA + ak]) = l;
            }
        }
        __syncthreads();

#pragma unroll
        for (int kb = 0; kb < BK; kb += 8) {
            // B fragments for this warp's 4 n-frags
            uint32_t bhf[4][2], blf[4][2];
#pragma unroll
            for (int nf = 0; nf < 4; nf++) {
                int i0, i1;
                if (!TB) {
                    int nb = wn * 32 + nf * 8 + gp;
                    i0 = (kb + tg) * PB + nb;
                    i1 = (kb + tg + 4) * PB + nb;
                } else {
                    int nb = wn * 32 + nf * 8 + gp;
                    i0 = nb * PA + kb + tg;
                    i1 = i0 + 4;
                }
                bhf[nf][0] = __float_as_uint(Bh[i0]);
                bhf[nf][1] = __float_as_uint(Bh[i1]);
                blf[nf][0] = __float_as_uint(Bl[i0]);
                blf[nf][1] = __float_as_uint(Bl[i1]);
            }
#pragma unroll
            for (int mf = 0; mf < 4; mf++) {
                int mb = wm * 64 + mf * 16 + gp;
                int j0 = mb * PA + kb + tg;
                int j1 = (mb + 8) * PA + kb + tg;
                uint32_t ahf[4] = { __float_as_uint(Ah[j0]), __float_as_uint(Ah[j1]),
                                    __float_as_uint(Ah[j0 + 4]), __float_as_uint(Ah[j1 + 4]) };
                uint32_t alf[4] = { __float_as_uint(Al[j0]), __float_as_uint(Al[j1]),
                                    __float_as_uint(Al[j0 + 4]), __float_as_uint(Al[j1 + 4]) };
#pragma unroll
                for (int nf = 0; nf < 4; nf++) {
                    mma8(acc[mf][nf], ahf, bhf[nf]);
                    mma8(acc[mf][nf], ahf, blf[nf]);
                    mma8(acc[mf][nf], alf, bhf[nf]);
                }
            }
        }
        __syncthreads();
    }

    // ---- store
#pragma unroll
    for (int mf = 0; mf < 4; mf++) {
#pragma unroll
        for (int nf = 0; nf < 4; nf++) {
            int n = n0 + wn * 32 + nf * 8 + 2 * tg;
#pragma unroll
            for (int h = 0; h < 2; h++) {
                int m = m0 + wm * 64 + mf * 16 + gp + h * 8;
                float2 v = make_float2(acc[mf][nf][2 * h], acc[mf][nf][2 * h + 1]);
                if (EPI == 1) {
                    v.x = v.x * SCALEV + ((n + 0 > m) ? NEGV : 0.f);
                    v.y = v.y * SCALEV + ((n + 1 > m) ? NEGV : 0.f);
                }
                long long ro = (long long)m * ldc;
                if (n + 1 < N) {
                    *reinterpret_cast<float2*>(C + ro + n) = v;
                } else {
                    if (n < N) C[ro + n] = v.x;
                    if (n + 1 < N) C[ro + n + 1] = v.y;
                }
            }
        }
    }
}

// ---------------- rmsnorm (in place), one block per row ----------------
__global__ void rmsnorm_k(float* __restrict__ x, const float* __restrict__ w, int len)
{
    float* row = x + (long long)blockIdx.x * len;
    const int tid = threadIdx.x;
    float ss = 0.f;
    for (int i = tid; i < len; i += 256) { float v = row[i]; ss += v * v; }
    __shared__ float red[8];
    __shared__ float sc_s;
#pragma unroll
    for (int o = 16; o; o >>= 1) ss += __shfl_xor_sync(0xffffffffu, ss, o);
    if ((tid & 31) == 0) red[tid >> 5] = ss;
    __syncthreads();
    if (tid == 0) {
        float t = 0.f;
#pragma unroll
        for (int i = 0; i < 8; i++) t += red[i];
        sc_s = rsqrtf(t / (float)len + EPSV);
    }
    __syncthreads();
    float sc = sc_s;
    for (int i = tid; i < len; i += 256) row[i] = row[i] * sc * w[i];
}

// ---- kv post: rmsnorm(c_kv)*w -> kvcat[0:512]; rope(k_pe) -> kvcat[512:576]
__global__ void kvpost_k(const float* __restrict__ kv, const float* __restrict__ w,
                         const float* __restrict__ fc, float* __restrict__ out)
{
    const int bs = blockIdx.x;
    const float* row = kv + (long long)bs * CAT;
    float* o = out + (long long)bs * CAT;
    const int tid = threadIdx.x;
    float ss = 0.f;
    for (int i = tid; i < KVL; i += 256) { float v = row[i]; ss += v * v; }
    __shared__ float red[8];
    __shared__ float sc_s;
#pragma unroll
    for (int oo = 16; oo; oo >>= 1) ss += __shfl_xor_sync(0xffffffffu, ss, oo);
    if ((tid & 31) == 0) red[tid >> 5] = ss;
    __syncthreads();
    if (tid == 0) {
        float t = 0.f;
#pragma unroll
        for (int i = 0; i < 8; i++) t += red[i];
        sc_s = rsqrtf(t / (float)KVL + EPSV);
    }
    __syncthreads();
    float sc = sc_s;
    for (int i = tid; i < KVL; i += 256) o[i] = row[i] * sc * w[i];
    if (tid < 32) {
        int s = bs & (SS - 1);
        float e  = row[KVL + 2 * tid];
        float od = row[KVL + 2 * tid + 1];
        float c  = fc[s * ROPE + 2 * tid];
        float sn = fc[s * ROPE + 2 * tid + 1];
        o[KVL + 2 * tid]     = e * c - od * sn;
        o[KVL + 2 * tid + 1] = e * sn + od * c;
    }
}

// ---- rope on q_pe, written into qcat[...,512:576] ----
__global__ void ropeq_k(const float* __restrict__ q, const float* __restrict__ fc,
                        float* __restrict__ qcat)
{
    const int bs = blockIdx.x;
    const int s = bs & (SS - 1);
    for (int t = threadIdx.x; t < HH * (ROPE / 2); t += 256) {
        int h = t >> 5, i = t & 31;
        const float* src = q + (long long)bs * QD + h * QKH + NOPE + 2 * i;
        float e = src[0], o = src[1];
        float c  = fc[s * ROPE + 2 * i];
        float sn = fc[s * ROPE + 2 * i + 1];
        float* dst = qcat + (long long)bs * (HH * CAT) + h * CAT + KVL + 2 * i;
        dst[0] = e * c - o * sn;
        dst[1] = e * sn + o * c;
    }
}

// ---- softmax over rows of 1024 ----
__global__ void softmax_k(float* __restrict__ S)
{
    float* row = S + (long long)blockIdx.x * 1024;
    const int tid = threadIdx.x;
    float v[4];
    float mx = -3.4e38f;
#pragma unroll
    for (int j = 0; j < 4; j++) { v[j] = row[tid + 256 * j]; mx = fmaxf(mx, v[j]); }
    __shared__ float red[8];
    __shared__ float bval;
#pragma unroll
    for (int o = 16; o; o >>= 1) mx = fmaxf(mx, __shfl_xor_sync(0xffffffffu, mx, o));
    if ((tid & 31) == 0) red[tid >> 5] = mx;
    __syncthreads();
    if (tid == 0) {
        float t = red[0];
#pragma unroll
        for (int i = 1; i < 8; i++) t = fmaxf(t, red[i]);
        bval = t;
    }
    __syncthreads();
    mx = bval;
    float sum = 0.f;
#pragma unroll
    for (int j = 0; j < 4; j++) { v[j] = __expf(v[j] - mx); sum += v[j]; }
    __syncthreads();
#pragma unroll
    for (int o = 16; o; o >>= 1) sum += __shfl_xor_sync(0xffffffffu, sum, o);
    if ((tid & 31) == 0) red[tid >> 5] = sum;
    __syncthreads();
    if (tid == 0) {
        float t = 0.f;
#pragma unroll
        for (int i = 0; i < 8; i++) t += red[i];
        bval = 1.f / t;
    }
    __syncthreads();
    float inv = bval;
#pragma unroll
    for (int j = 0; j < 4; j++) row[tid + 256 * j] = v[j] * inv;
}

// ---------------- host ----------------
extern "C" void kernel_launch(void* const* d_in, const int* in_sizes, int n_in,
                              void* d_out, int out_size)
{
    (void)in_sizes; (void)n_in; (void)out_size;
    const float* x      = (const float*)d_in[0];
    const float* fc     = (const float*)d_in[1];
    /* mask d_in[2] handled analytically (start_pos == 0, causal) */
    const float* wq_a   = (const float*)d_in[3];
    const float* qnw    = (const float*)d_in[4];
    const float* wq_b   = (const float*)d_in[5];
    const float* wkv_a  = (const float*)d_in[6];
    const float* kvnw   = (const float*)d_in[7];
    const float* wkv_b  = (const float*)d_in[8];
    const float* wo     = (const float*)d_in[9];
    float* out = (float*)d_out;

    float *qlora, *kv, *kvcat, *q, *qcat, *scores, *attn, *proj;
    cudaGetSymbolAddress((void**)&qlora,  g_qlora);
    cudaGetSymbolAddress((void**)&kv,     g_kv);
    cudaGetSymbolAddress((void**)&kvcat,  g_kvcat);
    cudaGetSymbolAddress((void**)&q,      g_q);
    cudaGetSymbolAddress((void**)&qcat,   g_qcat);
    cudaGetSymbolAddress((void**)&scores, g_scores);
    cudaGetSymbolAddress((void**)&attn,   g_attn);
    cudaGetSymbolAddress((void**)&proj,   g_proj);

    // 1. q_lora = x @ wq_a            [2048,1536]
    gemm_k<false, 0, false><<<dim3(12, 16, 1), 256>>>(
        x, wq_a, qlora, BS, QL, DIM, DIM, QL, QL, 0, 0, 0, 0, 0, 0, 1);
    // 2. kv = x @ wkv_a               [2048,576]
    gemm_k<false, 0, false><<<dim3(5, 16, 1), 256>>>(
        x, wkv_a, kv, BS, CAT, DIM, DIM, CAT, CAT, 0, 0, 0, 0, 0, 0, 1);
    // 3. rmsnorm(q_lora) in place
    rmsnorm_k<<<BS, 256>>>(qlora, qnw, QL);
    // 4. kv_norm + rope(k_pe) -> kvcat
    kvpost_k<<<BS, 256>>>(kv, kvnw, fc, kvcat);
    // 5. q = qlora_n @ wq_b           [2048,6144]
    gemm_k<false, 0, false><<<dim3(48, 16, 1), 256>>>(
        qlora, wq_b, q, BS, QD, QL, QL, QD, QD, 0, 0, 0, 0, 0, 0, 1);
    // 6. rope(q_pe) -> qcat[...,512:576]
    ropeq_k<<<BS, 256>>>(q, fc, qcat);
    // 7. q_abs (per head): qcat[...,0:512] = q_nope @ wkv_b[h,:128,:]
    gemm_k<false, 0, false><<<dim3(4, 16, HH), 256>>>(
        q, wkv_b, qcat, BS, KVL, NOPE,
        QD, KVL, HH * CAT,
        0, QKH, 0, (long long)(NOPE + VD) * KVL, 0, CAT, HH);
    // 8. scores (per b,h) = qcat @ kvcat^T, *SCALE + causal NEG
    gemm_k<true, 1, false><<<dim3(8, 8, BB * HH), 256>>>(
        qcat, kvcat, scores, SS, SS, CAT,
        HH * CAT, CAT, SS,
        (long long)SS * HH * CAT, CAT,
        (long long)SS * CAT, 0,
        (long long)HH * SS * SS, (long long)SS * SS, HH);
    // 9. softmax
    softmax_k<<<BB * HH * SS, 256>>>(scores);
    // 10. attn = P @ kv_norm (causal K-bound)
    gemm_k<false, 0, true><<<dim3(4, 8, BB * HH), 256>>>(
        scores, kvcat, attn, SS, KVL, SS,
        SS, CAT, HH * KVL,
        (long long)HH * SS * SS, (long long)SS * SS,
        (long long)SS * CAT, 0,
        (long long)SS * HH * KVL, KVL, HH);
    // 11. per-head V up-proj: proj[:, h*128+d] = attn_h @ wkv_b[h,128:,:]^T
    gemm_k<true, 0, false><<<dim3(1, 16, HH), 256>>>(
        attn, wkv_b + (long long)NOPE * KVL, proj, BS, VD, KVL,
        HH * KVL, KVL, DIM,
        0, KVL, 0, (long long)(NOPE + VD) * KVL, 0, VD, HH);
    // 12. out = proj @ wo             [2048,4096]
    gemm_k<false, 0, false><<<dim3(32, 16, 1), 256>>>(
        proj, wo, out, BS, DIM, DIM, DIM, DIM, DIM, 0, 0, 0, 0, 0, 0, 1);
}

// round 4
// speedup vs baseline: 3.3166x; 1.6307x over previous
#include <cuda_runtime.h>
#include <cuda_bf16.h>
#include <cuda_fp16.h>
#include <cstdint>

// ---------------- problem constants ----------------
#define BB   2
#define SS   1024
#define BS   2048          // B*S
#define DIM  4096
#define HH   32
#define QL   1536
#define KVL  512
#define NOPE 128
#define ROPE 64
#define VD   128
#define QKH  192           // NOPE+ROPE
#define CAT  576           // KVL+ROPE
#define QD   6144          // H*QKH

#define NEGV   (-1e9f)
#define SCALEV 0.07216878364870322f   // 192^-0.5
#define EPSV   1e-6f

// ---------------- scratch (device globals; no allocation allowed) ----------
__device__ float g_qlora[(long long)BS * QL];
__device__ float g_kv   [(long long)BS * CAT];
__device__ float g_kvcat[(long long)BS * CAT];          // [norm(c_kv) | rope(k_pe)]
__device__ float g_q    [(long long)BS * QD];
__device__ float g_qcat [(long long)BS * HH * CAT];     // [q_abs | rope(q_pe)] per head
__device__ float g_scores[64LL * 1024 * 1024];          // (b,h,s,t)
__device__ float g_attn [(long long)BS * HH * KVL];     // (bs,h,c)
__device__ float g_proj [(long long)BS * DIM];          // (bs, h*VD+d)

// ---------------- helpers ----------------
// split x,y into fp16 hi pair (packed) and fp16 lo pair (packed residuals)
__device__ __forceinline__ void split2(float x, float y, uint32_t& hi, uint32_t& lo) {
    __half hx = __float2half_rn(x), hy = __float2half_rn(y);
    float rx = x - __half2float(hx);
    float ry = y - __half2float(hy);
    __half2 h = __halves2half2(hx, hy);
    __half2 l = __floats2half2_rn(rx, ry);
    hi = *reinterpret_cast<uint32_t*>(&h);
    lo = *reinterpret_cast<uint32_t*>(&l);
}

__device__ __forceinline__ void mma16(float c[4], const uint32_t a[4], const uint32_t b[2]) {
    asm volatile(
        "mma.sync.aligned.m16n8k16.row.col.f32.f16.f16.f32 "
        "{%0,%1,%2,%3},{%4,%5,%6,%7},{%8,%9},{%0,%1,%2,%3};\n"
        : "+f"(c[0]), "+f"(c[1]), "+f"(c[2]), "+f"(c[3])
        : "r"(a[0]), "r"(a[1]), "r"(a[2]), "r"(a[3]), "r"(b[0]), "r"(b[1]));
}

// ---------------- split-FP16 3-pass tensor-core tiled GEMM ----------------
// C[m,n] = sum_k A[m,k] * B(k,n) ; TB: B stored [N,K] row-major (A @ B^T)
// EPI==1: scores epilogue (v*SCALE + causal NEG) with fully-masked tile skip
// CK: causal K-bound (k limited to m0+128) for P@V
// CTA tile 128x128, BK=16, 8 warps (2m x 4n), warp tile 64x32.
// Precision: x = hi(fp16)+lo(fp16); D += ah*bh + ah*bl + al*bh  (~2^-24 dropped)
// smem: tiles stored [row][k2] as u32 half2 k-pairs, pitch 12 (conflict-free:
//       frag addr = 12*gp + tg covers all 32 banks).
static const int BM = 128, BN = 128, BK = 16;
#define PK 12      // u32 pitch for [row][k2] tiles (k2 = 0..7 + pad 4)

template<bool TB, int EPI, bool CK>
__global__ __launch_bounds__(256, 2)
void gemm_k(const float* __restrict__ A, const float* __restrict__ Bp,
            float* __restrict__ C,
            int M, int N, int K,
            int lda, int ldb, int ldc,
            long long bA1, long long bA2,
            long long bB1, long long bB2,
            long long bC1, long long bC2, int nz2)
{
    const int z  = blockIdx.z;
    const int z1 = z / nz2;
    const int z2 = z - z1 * nz2;
    A  += z1 * bA1 + z2 * bA2;
    Bp += z1 * bB1 + z2 * bB2;
    C  += z1 * bC1 + z2 * bC2;

    const int m0  = blockIdx.y * BM;
    const int n0  = blockIdx.x * BN;
    const int tid = threadIdx.x;

    if (EPI == 1 && n0 >= m0 + BM) {
        for (int e = tid; e < BM * BN; e += 256) {
            int r = e >> 7, c = e & 127;
            if (n0 + c < N) C[(long long)(m0 + r) * ldc + n0 + c] = NEGV;
        }
        return;
    }

    __shared__ uint32_t Ah[BM * PK], Al[BM * PK];
    __shared__ uint32_t Bh[BN * PK], Bl[BN * PK];

    const int lane = tid & 31, warp = tid >> 5;
    const int wm = warp >> 2, wn = warp & 3;     // 2 x 4 warp grid
    const int gp = lane >> 2, tg = lane & 3;

    float acc[4][4][4];
#pragma unroll
    for (int i = 0; i < 4; i++)
#pragma unroll
        for (int j = 0; j < 4; j++)
#pragma unroll
            for (int r = 0; r < 4; r++) acc[i][j][r] = 0.f;

    int Keff = K;
    if (CK) { int km = m0 + BM; Keff = (km < K) ? km : K; }

    const int am = tid >> 2;          // 0..63 rows (A / TB-B loads), rows am, am+64
    const int ak = (tid & 3) << 2;    // k offset 0,4,8,12
    const int k2a = (tid & 3) << 1;   // k2 offset 0,2,4,6
    // non-TB B loads: thread -> n, k2 quad
    const int bnn  = tid & 127;       // n within tile
    const int bkh  = (tid >> 7) << 2; // k2 base 0 or 4

    for (int k0 = 0; k0 < Keff; k0 += BK) {
        // ---- A tile -> [m][k2] (hi/lo)
#pragma unroll
        for (int p = 0; p < 2; p++) {
            int m = am + (p << 6);
            float4 v = *reinterpret_cast<const float4*>(
                A + (long long)(m0 + m) * lda + k0 + ak);
            uint32_t h0, l0, h1, l1;
            split2(v.x, v.y, h0, l0);
            split2(v.z, v.w, h1, l1);
            Ah[m * PK + k2a]     = h0;  Ah[m * PK + k2a + 1] = h1;
            Al[m * PK + k2a]     = l0;  Al[m * PK + k2a + 1] = l1;
        }
        // ---- B tile -> [n][k2] (hi/lo)
        if (!TB) {   // gmem [k][n]: transpose in flight (coalesced along n)
#pragma unroll
            for (int q = 0; q < 4; q++) {
                int kk = bkh + q;                  // k2 index 0..7
                float f0 = 0.f, f1 = 0.f;
                if (n0 + bnn < N) {
                    f0 = Bp[(long long)(k0 + 2 * kk)     * ldb + n0 + bnn];
                    f1 = Bp[(long long)(k0 + 2 * kk + 1) * ldb + n0 + bnn];
                }
                uint32_t h, l;
                split2(f0, f1, h, l);
                Bh[bnn * PK + kk] = h;
                Bl[bnn * PK + kk] = l;
            }
        } else {     // gmem [n][k]: same pattern as A
#pragma unroll
            for (int p = 0; p < 2; p++) {
                int n = am + (p << 6);
                float4 v = make_float4(0.f, 0.f, 0.f, 0.f);
                if (n0 + n < N)
                    v = *reinterpret_cast<const float4*>(
                        Bp + (long long)(n0 + n) * ldb + k0 + ak);
                uint32_t h0, l0, h1, l1;
                split2(v.x, v.y, h0, l0);
                split2(v.z, v.w, h1, l1);
                Bh[n * PK + k2a]     = h0;  Bh[n * PK + k2a + 1] = h1;
                Bl[n * PK + k2a]     = l0;  Bl[n * PK + k2a + 1] = l1;
            }
        }
        __syncthreads();

        // ---- one k16 fragment step per chunk
        uint32_t bhf[4][2], blf[4][2];
#pragma unroll
        for (int nf = 0; nf < 4; nf++) {
            int nb = (wn << 5) + (nf << 3) + gp;
            bhf[nf][0] = Bh[nb * PK + tg];
            bhf[nf][1] = Bh[nb * PK + tg + 4];
            blf[nf][0] = Bl[nb * PK + tg];
            blf[nf][1] = Bl[nb * PK + tg + 4];
        }
#pragma unroll
        for (int mf = 0; mf < 4; mf++) {
            int mb = (wm << 6) + (mf << 4) + gp;
            int j0 = mb * PK + tg;
            int j1 = (mb + 8) * PK + tg;
            uint32_t ahf[4] = { Ah[j0], Ah[j1], Ah[j0 + 4], Ah[j1 + 4] };
            uint32_t alf[4] = { Al[j0], Al[j1], Al[j0 + 4], Al[j1 + 4] };
#pragma unroll
            for (int nf = 0; nf < 4; nf++) {
                mma16(acc[mf][nf], ahf, bhf[nf]);
                mma16(acc[mf][nf], ahf, blf[nf]);
                mma16(acc[mf][nf], alf, bhf[nf]);
            }
        }
        __syncthreads();
    }

    // ---- store (c0,c1: row gp; c2,c3: row gp+8; cols 2*tg,2*tg+1)
#pragma unroll
    for (int mf = 0; mf < 4; mf++) {
#pragma unroll
        for (int nf = 0; nf < 4; nf++) {
            int n = n0 + (wn << 5) + (nf << 3) + 2 * tg;
#pragma unroll
            for (int h = 0; h < 2; h++) {
                int m = m0 + (wm << 6) + (mf << 4) + gp + h * 8;
                float2 v = make_float2(acc[mf][nf][2 * h], acc[mf][nf][2 * h + 1]);
                if (EPI == 1) {
                    v.x = v.x * SCALEV + ((n + 0 > m) ? NEGV : 0.f);
                    v.y = v.y * SCALEV + ((n + 1 > m) ? NEGV : 0.f);
                }
                long long ro = (long long)m * ldc;
                if (n + 1 < N) {
                    *reinterpret_cast<float2*>(C + ro + n) = v;
                } else {
                    if (n < N) C[ro + n] = v.x;
                    if (n + 1 < N) C[ro + n + 1] = v.y;
                }
            }
        }
    }
}

// ---------------- rmsnorm (in place), one block per row ----------------
__global__ void rmsnorm_k(float* __restrict__ x, const float* __restrict__ w, int len)
{
    float* row = x + (long long)blockIdx.x * len;
    const int tid = threadIdx.x;
    float ss = 0.f;
    for (int i = tid; i < len; i += 256) { float v = row[i]; ss += v * v; }
    __shared__ float red[8];
    __shared__ float sc_s;
#pragma unroll
    for (int o = 16; o; o >>= 1) ss += __shfl_xor_sync(0xffffffffu, ss, o);
    if ((tid & 31) == 0) red[tid >> 5] = ss;
    __syncthreads();
    if (tid == 0) {
        float t = 0.f;
#pragma unroll
        for (int i = 0; i < 8; i++) t += red[i];
        sc_s = rsqrtf(t / (float)len + EPSV);
    }
    __syncthreads();
    float sc = sc_s;
    for (int i = tid; i < len; i += 256) row[i] = row[i] * sc * w[i];
}

// ---- kv post: rmsnorm(c_kv)*w -> kvcat[0:512]; rope(k_pe) -> kvcat[512:576]
__global__ void kvpost_k(const float* __restrict__ kv, const float* __restrict__ w,
                         const float* __restrict__ fc, float* __restrict__ out)
{
    const int bs = blockIdx.x;
    const float* row = kv + (long long)bs * CAT;
    float* o = out + (long long)bs * CAT;
    const int tid = threadIdx.x;
    float ss = 0.f;
    for (int i = tid; i < KVL; i += 256) { float v = row[i]; ss += v * v; }
    __shared__ float red[8];
    __shared__ float sc_s;
#pragma unroll
    for (int oo = 16; oo; oo >>= 1) ss += __shfl_xor_sync(0xffffffffu, ss, oo);
    if ((tid & 31) == 0) red[tid >> 5] = ss;
    __syncthreads();
    if (tid == 0) {
        float t = 0.f;
#pragma unroll
        for (int i = 0; i < 8; i++) t += red[i];
        sc_s = rsqrtf(t / (float)KVL + EPSV);
    }
    __syncthreads();
    float sc = sc_s;
    for (int i = tid; i < KVL; i += 256) o[i] = row[i] * sc * w[i];
    if (tid < 32) {
        int s = bs & (SS - 1);
        float e  = row[KVL + 2 * tid];
        float od = row[KVL + 2 * tid + 1];
        float c  = fc[s * ROPE + 2 * tid];
        float sn = fc[s * ROPE + 2 * tid + 1];
        o[KVL + 2 * tid]     = e * c - od * sn;
        o[KVL + 2 * tid + 1] = e * sn + od * c;
    }
}

// ---- rope on q_pe, written into qcat[...,512:576] ----
__global__ void ropeq_k(const float* __restrict__ q, const float* __restrict__ fc,
                        float* __restrict__ qcat)
{
    const int bs = blockIdx.x;
    const int s = bs & (SS - 1);
    for (int t = threadIdx.x; t < HH * (ROPE / 2); t += 256) {
        int h = t >> 5, i = t & 31;
        const float* src = q + (long long)bs * QD + h * QKH + NOPE + 2 * i;
        float e = src[0], o = src[1];
        float c  = fc[s * ROPE + 2 * i];
        float sn = fc[s * ROPE + 2 * i + 1];
        float* dst = qcat + (long long)bs * (HH * CAT) + h * CAT + KVL + 2 * i;
        dst[0] = e * c - o * sn;
        dst[1] = e * sn + o * c;
    }
}

// ---- softmax over rows of 1024 ----
__global__ void softmax_k(float* __restrict__ S)
{
    float* row = S + (long long)blockIdx.x * 1024;
    const int tid = threadIdx.x;
    float v[4];
    float mx = -3.4e38f;
#pragma unroll
    for (int j = 0; j < 4; j++) { v[j] = row[tid + 256 * j]; mx = fmaxf(mx, v[j]); }
    __shared__ float red[8];
    __shared__ float bval;
#pragma unroll
    for (int o = 16; o; o >>= 1) mx = fmaxf(mx, __shfl_xor_sync(0xffffffffu, mx, o));
    if ((tid & 31) == 0) red[tid >> 5] = mx;
    __syncthreads();
    if (tid == 0) {
        float t = red[0];
#pragma unroll
        for (int i = 1; i < 8; i++) t = fmaxf(t, red[i]);
        bval = t;
    }
    __syncthreads();
    mx = bval;
    float sum = 0.f;
#pragma unroll
    for (int j = 0; j < 4; j++) { v[j] = __expf(v[j] - mx); sum += v[j]; }
    __syncthreads();
#pragma unroll
    for (int o = 16; o; o >>= 1) sum += __shfl_xor_sync(0xffffffffu, sum, o);
    if ((tid & 31) == 0) red[tid >> 5] = sum;
    __syncthreads();
    if (tid == 0) {
        float t = 0.f;
#pragma unroll
        for (int i = 0; i < 8; i++) t += red[i];
        bval = 1.f / t;
    }
    __syncthreads();
    float inv = bval;
#pragma unroll
    for (int j = 0; j < 4; j++) row[tid + 256 * j] = v[j] * inv;
}

// ---------------- host ----------------
extern "C" void kernel_launch(void* const* d_in, const int* in_sizes, int n_in,
                              void* d_out, int out_size)
{
    (void)in_sizes; (void)n_in; (void)out_size;
    const float* x      = (const float*)d_in[0];
    const float* fc     = (const float*)d_in[1];
    /* mask d_in[2] handled analytically (start_pos == 0, causal) */
    const float* wq_a   = (const float*)d_in[3];
    const float* qnw    = (const float*)d_in[4];
    const float* wq_b   = (const float*)d_in[5];
    const float* wkv_a  = (const float*)d_in[6];
    const float* kvnw   = (const float*)d_in[7];
    const float* wkv_b  = (const float*)d_in[8];
    const float* wo     = (const float*)d_in[9];
    float* out = (float*)d_out;

    float *qlora, *kv, *kvcat, *q, *qcat, *scores, *attn, *proj;
    cudaGetSymbolAddress((void**)&qlora,  g_qlora);
    cudaGetSymbolAddress((void**)&kv,     g_kv);
    cudaGetSymbolAddress((void**)&kvcat,  g_kvcat);
    cudaGetSymbolAddress((void**)&q,      g_q);
    cudaGetSymbolAddress((void**)&qcat,   g_qcat);
    cudaGetSymbolAddress((void**)&scores, g_scores);
    cudaGetSymbolAddress((void**)&attn,   g_attn);
    cudaGetSymbolAddress((void**)&proj,   g_proj);

    // 1. q_lora = x @ wq_a            [2048,1536]
    gemm_k<false, 0, false><<<dim3(12, 16, 1), 256>>>(
        x, wq_a, qlora, BS, QL, DIM, DIM, QL, QL, 0, 0, 0, 0, 0, 0, 1);
    // 2. kv = x @ wkv_a               [2048,576]
    gemm_k<false, 0, false><<<dim3(5, 16, 1), 256>>>(
        x, wkv_a, kv, BS, CAT, DIM, DIM, CAT, CAT, 0, 0, 0, 0, 0, 0, 1);
    // 3. rmsnorm(q_lora) in place
    rmsnorm_k<<<BS, 256>>>(qlora, qnw, QL);
    // 4. kv_norm + rope(k_pe) -> kvcat
    kvpost_k<<<BS, 256>>>(kv, kvnw, fc, kvcat);
    // 5. q = qlora_n @ wq_b           [2048,6144]
    gemm_k<false, 0, false><<<dim3(48, 16, 1), 256>>>(
        qlora, wq_b, q, BS, QD, QL, QL, QD, QD, 0, 0, 0, 0, 0, 0, 1);
    // 6. rope(q_pe) -> qcat[...,512:576]
    ropeq_k<<<BS, 256>>>(q, fc, qcat);
    // 7. q_abs (per head): qcat[...,0:512] = q_nope @ wkv_b[h,:128,:]
    gemm_k<false, 0, false><<<dim3(4, 16, HH), 256>>>(
        q, wkv_b, qcat, BS, KVL, NOPE,
        QD, KVL, HH * CAT,
        0, QKH, 0, (long long)(NOPE + VD) * KVL, 0, CAT, HH);
    // 8. scores (per b,h) = qcat @ kvcat^T, *SCALE + causal NEG
    gemm_k<true, 1, false><<<dim3(8, 8, BB * HH), 256>>>(
        qcat, kvcat, scores, SS, SS, CAT,
        HH * CAT, CAT, SS,
        (long long)SS * HH * CAT, CAT,
        (long long)SS * CAT, 0,
        (long long)HH * SS * SS, (long long)SS * SS, HH);
    // 9. softmax
    softmax_k<<<BB * HH * SS, 256>>>(scores);
    // 10. attn = P @ kv_norm (causal K-bound)
    gemm_k<false, 0, true><<<dim3(4, 8, BB * HH), 256>>>(
        scores, kvcat, attn, SS, KVL, SS,
        SS, CAT, HH * KVL,
        (long long)HH * SS * SS, (long long)SS * SS,
        (long long)SS * CAT, 0,
        (long long)SS * HH * KVL, KVL, HH);
    // 11. per-head V up-proj: proj[:, h*128+d] = attn_h @ wkv_b[h,128:,:]^T
    gemm_k<true, 0, false><<<dim3(1, 16, HH), 256>>>(
        attn, wkv_b + (long long)NOPE * KVL, proj, BS, VD, KVL,
        HH * KVL, KVL, DIM,
        0, KVL, 0, (long long)(NOPE + VD) * KVL, 0, VD, HH);
    // 12. out = proj @ wo             [2048,4096]
    gemm_k<false, 0, false><<<dim3(32, 16, 1), 256>>>(
        proj, wo, out, BS, DIM, DIM, DIM, DIM, DIM, 0, 0, 0, 0, 0, 0, 1);
}